// round 4
// baseline (speedup 1.0000x reference)
#include <cuda_runtime.h>
#include <stdint.h>

#define FULL 0xffffffffu
#define NI_CAP 50176   // >= num_items (50000), multiple of 32

// Scratch tables (device globals: allowed; no allocation APIs used).
__device__ float g_V[NI_CAP * 32];   // g_V[it][d]  = sum_e W_bil[d][e] * item_e[e]
__device__ float g_C1[NI_CAP * 8];   // g_C1[it][j] = sum_e W1[j][64+e] * item_e[e]
__device__ int   g_mask_is_i32;

// ---------------------------------------------------------------------------
// Mask dtype detection: numpy bool (1B) vs widened int32 (4B) per element.
__global__ void detect_mask_kernel(const int* __restrict__ mask_as_i32, int n_i32) {
    __shared__ int bad;
    if (threadIdx.x == 0) bad = 0;
    __syncthreads();
    int local = 0;
    for (int i = threadIdx.x; i < n_i32; i += blockDim.x) {
        int v = mask_as_i32[i];
        if (v != 0 && v != 1) local = 1;
    }
    if (local) atomicOr(&bad, 1);
    __syncthreads();
    if (threadIdx.x == 0) g_mask_is_i32 = bad ? 0 : 1;
}

// ---------------------------------------------------------------------------
// Per-item precompute: one warp per item, lane d owns output dim d.
__global__ __launch_bounds__(256)
void precompute_kernel(const float* __restrict__ item_table,
                       const float* __restrict__ W_bil,
                       const float* __restrict__ W1,
                       int NI)
{
    __shared__ float Wt[32 * 32];    // Wt[e*32+d] = W_bil[d][e]
    __shared__ float W1c[8 * 32];    // W1c[j*32+e] = W1[j][64+e]
    const int tid = threadIdx.x;
    for (int i = tid; i < 1024; i += 256)
        Wt[(i & 31) * 32 + (i >> 5)] = W_bil[i];
    for (int i = tid; i < 256; i += 256)
        W1c[i] = W1[(i >> 5) * 96 + 64 + (i & 31)];
    __syncthreads();

    const int it = blockIdx.x * 8 + (tid >> 5);
    const int d  = tid & 31;
    const bool ok = (it < NI);
    float ied = ok ? item_table[(size_t)it * 32 + d] : 0.0f;
    float v = 0.0f, c = 0.0f;
#pragma unroll
    for (int e = 0; e < 32; e++) {
        float iee = __shfl_sync(FULL, ied, e);
        v = fmaf(Wt[e * 32 + d], iee, v);
        c = fmaf(W1c[(d & 7) * 32 + e], iee, c);
    }
    if (ok) {
        g_V[(size_t)it * 32 + d] = v;
        if (d < 8) g_C1[(size_t)it * 8 + d] = c;
    }
}

// ---------------------------------------------------------------------------
// Main kernel: 4 pairs/warp, 8 lanes/pair, lane owns 4 dims (float4).
__global__ __launch_bounds__(256)
void bilinear_kernel(const int* __restrict__ item_inputs,
                     const int* __restrict__ member_ids,
                     const void* __restrict__ member_mask,
                     const float* __restrict__ user_table,
                     const float* __restrict__ item_table,
                     const float* __restrict__ b_bil,
                     const float* __restrict__ b1,
                     const float* __restrict__ W1,
                     const float* __restrict__ W2,
                     const float* __restrict__ b2,
                     float* __restrict__ out,
                     int B)
{
    __shared__ float W1s[8 * 64];    // wA (cols 0..31) | wB (cols 32..63) per j
    __shared__ float b1s[8], W2s[8];
    __shared__ float sc[2];          // {b_bil, b2}

    const int tid = threadIdx.x;
    for (int i = tid; i < 512; i += 256)
        W1s[i] = W1[(i >> 6) * 96 + (i & 63)];
    if (tid < 8) { b1s[tid] = b1[tid]; W2s[tid] = W2[tid]; }
    if (tid == 0) { sc[0] = b_bil[0]; sc[1] = b2[0]; }
    __syncthreads();

    const int lane  = tid & 31;
    const int sub   = lane >> 3;
    const int sl    = lane & 7;
    const int sbase = lane & 24;

    const int gb = (blockIdx.x * 8 + (tid >> 5)) * 4;
    if (gb >= B) return;
    const int b  = gb + sub;
    const int bc = min(b, B - 1);

    const float bbil = sc[0];
    const float bb2  = sc[1];
    const bool mask_i32 = (g_mask_is_i32 != 0);

    // item embedding + precomputed v = W_bil @ ie (both gathered by row)
    const int it = __ldg(item_inputs + bc);
    const float4 ie = *reinterpret_cast<const float4*>(item_table + (size_t)it * 32 + sl * 4);
    const float4 v  = *reinterpret_cast<const float4*>(g_V        + (size_t)it * 32 + sl * 4);

    // member ids + mask packed into sign bit; 2 members per lane
    int pk0, pk1;
    {
        long off = (long)gb * 16 + lane * 2;
        long maxoff = (long)B * 16 - 2;
        if (off > maxoff) off = maxoff;
        int2 mi = *reinterpret_cast<const int2*>(member_ids + off);
        int m0, m1;
        if (mask_i32) {
            int2 mm = *reinterpret_cast<const int2*>((const int*)member_mask + off);
            m0 = mm.x; m1 = mm.y;
        } else {
            unsigned short s = *reinterpret_cast<const unsigned short*>(
                (const unsigned char*)member_mask + off);
            m0 = s & 0xff; m1 = (s >> 8) & 0xff;
        }
        pk0 = mi.x | (m0 ? (int)0x80000000 : 0);
        pk1 = mi.y | (m1 ? (int)0x80000000 : 0);
    }

    // member loop: chunks of 4 to keep 4 LDG.128 in flight
    float4 fu = make_float4(0.f, 0.f, 0.f, 0.f);
#pragma unroll
    for (int c = 0; c < 4; c++) {
        int pks[4];
        float4 u[4];
        float p[4];
#pragma unroll
        for (int k = 0; k < 4; k++) {
            int m = c * 4 + k;
            pks[k] = __shfl_sync(FULL, (m & 1) ? pk1 : pk0, sbase + (m >> 1));
        }
#pragma unroll
        for (int k = 0; k < 4; k++)
            u[k] = *reinterpret_cast<const float4*>(
                user_table + (size_t)(pks[k] & 0x7fffffff) * 32 + sl * 4);
#pragma unroll
        for (int k = 0; k < 4; k++) {
            float t = u[k].x * v.x;
            t = fmaf(u[k].y, v.y, t);
            t = fmaf(u[k].z, v.z, t);
            p[k] = fmaf(u[k].w, v.w, t);
        }
#pragma unroll
        for (int s = 1; s <= 4; s <<= 1) {
#pragma unroll
            for (int k = 0; k < 4; k++)
                p[k] += __shfl_xor_sync(FULL, p[k], s);
        }
#pragma unroll
        for (int k = 0; k < 4; k++) {
            float w = (pks[k] < 0) ? (p[k] + bbil) : 0.0f;
            fu.x = fmaf(w, u[k].x, fu.x);
            fu.y = fmaf(w, u[k].y, fu.y);
            fu.z = fmaf(w, u[k].z, fu.z);
            fu.w = fmaf(w, u[k].w, fu.w);
        }
    }

    // MLP: h[j] = sum_d (wA[j,d]*fu[d]*ie[d] + wB[j,d]*fu[d]) + c1[j]
    const float4 pr = make_float4(fu.x * ie.x, fu.y * ie.y, fu.z * ie.z, fu.w * ie.w);
    float h[8];
#pragma unroll
    for (int j = 0; j < 8; j++) {
        const float4 wA = *reinterpret_cast<const float4*>(&W1s[j * 64 + sl * 4]);
        const float4 wB = *reinterpret_cast<const float4*>(&W1s[j * 64 + 32 + sl * 4]);
        float t = wA.x * pr.x;
        t = fmaf(wA.y, pr.y, t);
        t = fmaf(wA.z, pr.z, t);
        t = fmaf(wA.w, pr.w, t);
        t = fmaf(wB.x, fu.x, t);
        t = fmaf(wB.y, fu.y, t);
        t = fmaf(wB.z, fu.z, t);
        h[j] = fmaf(wB.w, fu.w, t);
    }

    // 8x8 transpose-reduce in 7 shuffles: lane sl ends owning total h[sl]
    float a0, a1, a2, a3;
    {
        const bool hi = (sl & 4) != 0;
#pragma unroll
        for (int k = 0; k < 4; k++) {
            float give = hi ? h[k] : h[k + 4];
            float got  = __shfl_xor_sync(FULL, give, 4);
            float keep = hi ? h[k + 4] : h[k];
            (k == 0 ? a0 : k == 1 ? a1 : k == 2 ? a2 : a3) = keep + got;
        }
    }
    float c0, c1r;
    {
        const bool hi = (sl & 2) != 0;
        float g0 = hi ? a0 : a2;
        float g1 = hi ? a1 : a3;
        float r0 = __shfl_xor_sync(FULL, g0, 2);
        float r1 = __shfl_xor_sync(FULL, g1, 2);
        c0  = (hi ? a2 : a0) + r0;
        c1r = (hi ? a3 : a1) + r1;
    }
    float hj;
    {
        const bool hi = (sl & 1) != 0;
        float give = hi ? c0 : c1r;
        float got  = __shfl_xor_sync(FULL, give, 1);
        hj = (hi ? c1r : c0) + got;
    }

    // lane sl handles hidden unit j = sl; add precomputed item term + bias
    float c1v = g_C1[(size_t)it * 8 + sl];
    float r = fmaxf(hj + c1v + b1s[sl], 0.0f) * W2s[sl];
    r += __shfl_xor_sync(FULL, r, 1);
    r += __shfl_xor_sync(FULL, r, 2);
    r += __shfl_xor_sync(FULL, r, 4);
    if (sl == 0 && b < B)
        out[b] = 1.0f / (1.0f + __expf(-(r + bb2)));
}

extern "C" void kernel_launch(void* const* d_in, const int* in_sizes, int n_in,
                              void* d_out, int out_size) {
    const int*   item_inputs = (const int*)d_in[0];
    const int*   member_ids  = (const int*)d_in[1];
    const void*  member_mask = d_in[2];
    const float* user_table  = (const float*)d_in[3];
    const float* item_table  = (const float*)d_in[4];
    const float* W_bil       = (const float*)d_in[5];
    const float* b_bil       = (const float*)d_in[6];
    const float* W1          = (const float*)d_in[7];
    const float* b1          = (const float*)d_in[8];
    const float* W2          = (const float*)d_in[9];
    const float* b2          = (const float*)d_in[10];
    float* out = (float*)d_out;

    const int B  = in_sizes[0];
    int NI = in_sizes[4] / 32;
    if (NI > NI_CAP) NI = NI_CAP;

    int n_scan = in_sizes[2] / 4;
    if (n_scan > 4096) n_scan = 4096;
    detect_mask_kernel<<<1, 256>>>((const int*)member_mask, n_scan);

    precompute_kernel<<<(NI + 7) / 8, 256>>>(item_table, W_bil, W1, NI);

    const int grid = (B + 31) / 32;   // 8 warps * 4 pairs per block
    bilinear_kernel<<<grid, 256>>>(item_inputs, member_ids, member_mask,
                                   user_table, item_table, b_bil,
                                   b1, W1, W2, b2, out, B);
}

// round 5
// speedup vs baseline: 1.0305x; 1.0305x over previous
#include <cuda_runtime.h>
#include <stdint.h>

#define FULL 0xffffffffu
#define NI_CAP 50176   // >= num_items (50000), multiple of 32

// Scratch (device globals: allowed; no allocation APIs used).
__device__ float g_V[NI_CAP * 32];   // g_V[it][d]  = sum_e W_bil[d][e] * item_e[e]
__device__ float g_C1[NI_CAP * 8];   // g_C1[it][j] = sum_e W1[j][64+e] * item_e[e]
__device__ int   g_mask_is_i32;

// ---------------------------------------------------------------------------
// Per-item precompute (one warp per item) + mask-dtype detection in block 0.
__global__ __launch_bounds__(256)
void precompute_kernel(const float* __restrict__ item_table,
                       const float* __restrict__ W_bil,
                       const float* __restrict__ W1,
                       const int* __restrict__ mask_as_i32,
                       int n_scan, int NI)
{
    __shared__ float Wt[32 * 32];    // Wt[e*32+d] = W_bil[d][e]
    __shared__ float W1c[8 * 32];    // W1c[j*32+e] = W1[j][64+e]
    __shared__ int sbad;
    const int tid = threadIdx.x;

    if (blockIdx.x == 0) {
        // numpy bool (1B/elem) vs widened int32: reading bool bytes as i32
        // yields values like 0x0101 whenever a row has >=2 valid members.
        if (tid == 0) sbad = 0;
        __syncthreads();
        int bad = 0;
        for (int i = tid; i < n_scan; i += 256) {
            int v = mask_as_i32[i];
            if (v & ~1) bad = 1;
        }
        unsigned any = __ballot_sync(FULL, bad);
        if (any && (tid & 31) == 0) atomicOr(&sbad, 1);
        __syncthreads();
        if (tid == 0) g_mask_is_i32 = sbad ? 0 : 1;
    }

    for (int i = tid; i < 1024; i += 256)
        Wt[(i & 31) * 32 + (i >> 5)] = W_bil[i];
    for (int i = tid; i < 256; i += 256)
        W1c[i] = W1[(i >> 5) * 96 + 64 + (i & 31)];
    __syncthreads();

    const int it = blockIdx.x * 8 + (tid >> 5);
    const int d  = tid & 31;
    const bool ok = (it < NI);
    float ied = ok ? item_table[(size_t)it * 32 + d] : 0.0f;
    float v = 0.0f, c = 0.0f;
#pragma unroll
    for (int e = 0; e < 32; e++) {
        float iee = __shfl_sync(FULL, ied, e);
        v = fmaf(Wt[e * 32 + d], iee, v);
        c = fmaf(W1c[(d & 7) * 32 + e], iee, c);
    }
    if (ok) {
        g_V[(size_t)it * 32 + d] = v;
        if (d < 8) g_C1[(size_t)it * 8 + d] = c;
    }
}

// ---------------------------------------------------------------------------
// Main kernel: 4 pairs/warp, 8 lanes/pair, lane owns 4 dims (float4).
__global__ __launch_bounds__(256, 6)
void bilinear_kernel(const int* __restrict__ item_inputs,
                     const int* __restrict__ member_ids,
                     const void* __restrict__ member_mask,
                     const float* __restrict__ user_table,
                     const float* __restrict__ item_table,
                     const float* __restrict__ b_bil,
                     const float* __restrict__ b1,
                     const float* __restrict__ W1,
                     const float* __restrict__ W2,
                     const float* __restrict__ b2,
                     float* __restrict__ out,
                     int B)
{
    __shared__ float W1s[8 * 64];    // wA (cols 0..31) | wB (cols 32..63) per j
    __shared__ float b1s[8], W2s[8];
    __shared__ float sc[2];          // {b_bil, b2}

    const int tid = threadIdx.x;
    for (int i = tid; i < 512; i += 256)
        W1s[i] = W1[(i >> 6) * 96 + (i & 63)];
    if (tid < 8) { b1s[tid] = b1[tid]; W2s[tid] = W2[tid]; }
    if (tid == 0) { sc[0] = b_bil[0]; sc[1] = b2[0]; }
    __syncthreads();

    const int lane  = tid & 31;
    const int sub   = lane >> 3;
    const int sl    = lane & 7;
    const int sbase = lane & 24;

    const int gb = (blockIdx.x * 8 + (tid >> 5)) * 4;
    if (gb >= B) return;
    const int b  = gb + sub;
    const int bc = min(b, B - 1);

    const float bbil = sc[0];
    const float bb2  = sc[1];
    const bool mask_i32 = (g_mask_is_i32 != 0);

    // item-side gathers (issued early; independent of member loads)
    const int it = __ldg(item_inputs + bc);
    const float4 v  = *reinterpret_cast<const float4*>(g_V        + (size_t)it * 32 + sl * 4);
    const float4 ie = *reinterpret_cast<const float4*>(item_table + (size_t)it * 32 + sl * 4);

    // member ids + mask packed into sign bit; lane holds members {2*lane, 2*lane+1}
    int pk0, pk1;
    {
        long off = (long)gb * 16 + lane * 2;
        long maxoff = (long)B * 16 - 2;
        if (off > maxoff) off = maxoff;
        int2 mi = *reinterpret_cast<const int2*>(member_ids + off);
        int m0, m1;
        if (mask_i32) {
            int2 mm = *reinterpret_cast<const int2*>((const int*)member_mask + off);
            m0 = mm.x; m1 = mm.y;
        } else {
            unsigned short s = *reinterpret_cast<const unsigned short*>(
                (const unsigned char*)member_mask + off);
            m0 = s & 0xff; m1 = (s >> 8) & 0xff;
        }
        pk0 = mi.x | (m0 ? (int)0x80000000 : 0);
        pk1 = mi.y | (m1 ? (int)0x80000000 : 0);
    }

    const bool hi4 = (sl & 4) != 0;
    const bool hi2 = (sl & 2) != 0;

    // member loop: 4 chunks of 4 members; 12 shuffles per chunk
    float4 fu = make_float4(0.f, 0.f, 0.f, 0.f);
#pragma unroll
    for (int c = 0; c < 4; c++) {
        const int src0 = sbase + 2 * c;
        const int pka = __shfl_sync(FULL, pk0, src0);      // member 4c
        const int pkb = __shfl_sync(FULL, pk1, src0);      // member 4c+1
        const int pkc = __shfl_sync(FULL, pk0, src0 + 1);  // member 4c+2
        const int pkd = __shfl_sync(FULL, pk1, src0 + 1);  // member 4c+3

        const float4 u0 = *reinterpret_cast<const float4*>(
            user_table + (size_t)(pka & 0x7fffffff) * 32 + sl * 4);
        const float4 u1 = *reinterpret_cast<const float4*>(
            user_table + (size_t)(pkb & 0x7fffffff) * 32 + sl * 4);
        const float4 u2 = *reinterpret_cast<const float4*>(
            user_table + (size_t)(pkc & 0x7fffffff) * 32 + sl * 4);
        const float4 u3 = *reinterpret_cast<const float4*>(
            user_table + (size_t)(pkd & 0x7fffffff) * 32 + sl * 4);

        float p0 = fmaf(u0.w, v.w, fmaf(u0.z, v.z, fmaf(u0.y, v.y, u0.x * v.x)));
        float p1 = fmaf(u1.w, v.w, fmaf(u1.z, v.z, fmaf(u1.y, v.y, u1.x * v.x)));
        float p2 = fmaf(u2.w, v.w, fmaf(u2.z, v.z, fmaf(u2.y, v.y, u2.x * v.x)));
        float p3 = fmaf(u3.w, v.w, fmaf(u3.z, v.z, fmaf(u3.y, v.y, u3.x * v.x)));

        // batched reduce: 4 sums over 8 lanes in 4 shuffles.
        // After: lanes {0,1}->m0, {2,3}->m1, {4,5}->m2, {6,7}->m3 hold totals.
        float g0 = __shfl_xor_sync(FULL, hi4 ? p0 : p2, 4);
        float g1 = __shfl_xor_sync(FULL, hi4 ? p1 : p3, 4);
        float q0 = (hi4 ? p2 : p0) + g0;
        float q1 = (hi4 ? p3 : p1) + g1;
        float g2 = __shfl_xor_sync(FULL, hi2 ? q0 : q1, 2);
        float r  = (hi2 ? q1 : q0) + g2;
        float s  = r + __shfl_xor_sync(FULL, r, 1);

        // mask+bias at owner lanes, then broadcast the 4 weights
        int mypk = hi4 ? (hi2 ? pkd : pkc) : (hi2 ? pkb : pka);
        float wv = (mypk < 0) ? (s + bbil) : 0.0f;
        float w0 = __shfl_sync(FULL, wv, sbase + 0);
        float w1 = __shfl_sync(FULL, wv, sbase + 2);
        float w2 = __shfl_sync(FULL, wv, sbase + 4);
        float w3 = __shfl_sync(FULL, wv, sbase + 6);

        fu.x = fmaf(w3, u3.x, fmaf(w2, u2.x, fmaf(w1, u1.x, fmaf(w0, u0.x, fu.x))));
        fu.y = fmaf(w3, u3.y, fmaf(w2, u2.y, fmaf(w1, u1.y, fmaf(w0, u0.y, fu.y))));
        fu.z = fmaf(w3, u3.z, fmaf(w2, u2.z, fmaf(w1, u1.z, fmaf(w0, u0.z, fu.z))));
        fu.w = fmaf(w3, u3.w, fmaf(w2, u2.w, fmaf(w1, u1.w, fmaf(w0, u0.w, fu.w))));
    }

    // MLP: h[j] = sum_d (wA[j,d]*fu[d]*ie[d] + wB[j,d]*fu[d])  (+ item term via g_C1)
    const float4 pr = make_float4(fu.x * ie.x, fu.y * ie.y, fu.z * ie.z, fu.w * ie.w);
    float h[8];
#pragma unroll
    for (int j = 0; j < 8; j++) {
        const float4 wA = *reinterpret_cast<const float4*>(&W1s[j * 64 + sl * 4]);
        const float4 wB = *reinterpret_cast<const float4*>(&W1s[j * 64 + 32 + sl * 4]);
        float t = wA.x * pr.x;
        t = fmaf(wA.y, pr.y, t);
        t = fmaf(wA.z, pr.z, t);
        t = fmaf(wA.w, pr.w, t);
        t = fmaf(wB.x, fu.x, t);
        t = fmaf(wB.y, fu.y, t);
        t = fmaf(wB.z, fu.z, t);
        h[j] = fmaf(wB.w, fu.w, t);
    }

    // 8x8 transpose-reduce in 7 shuffles: lane sl ends owning total h[sl]
    float a0, a1, a2, a3;
    {
#pragma unroll
        for (int k = 0; k < 4; k++) {
            float give = hi4 ? h[k] : h[k + 4];
            float got  = __shfl_xor_sync(FULL, give, 4);
            float keep = hi4 ? h[k + 4] : h[k];
            (k == 0 ? a0 : k == 1 ? a1 : k == 2 ? a2 : a3) = keep + got;
        }
    }
    float c0, c1r;
    {
        float r0 = __shfl_xor_sync(FULL, hi2 ? a0 : a2, 2);
        float r1 = __shfl_xor_sync(FULL, hi2 ? a1 : a3, 2);
        c0  = (hi2 ? a2 : a0) + r0;
        c1r = (hi2 ? a3 : a1) + r1;
    }
    float hj;
    {
        const bool hi1 = (sl & 1) != 0;
        float got = __shfl_xor_sync(FULL, hi1 ? c0 : c1r, 1);
        hj = (hi1 ? c1r : c0) + got;
    }

    // lane sl handles hidden unit j = sl
    float c1v = g_C1[(size_t)it * 8 + sl];
    float rr = fmaxf(hj + c1v + b1s[sl], 0.0f) * W2s[sl];
    rr += __shfl_xor_sync(FULL, rr, 1);
    rr += __shfl_xor_sync(FULL, rr, 2);
    rr += __shfl_xor_sync(FULL, rr, 4);
    if (sl == 0 && b < B)
        out[b] = 1.0f / (1.0f + __expf(-(rr + bb2)));
}

extern "C" void kernel_launch(void* const* d_in, const int* in_sizes, int n_in,
                              void* d_out, int out_size) {
    const int*   item_inputs = (const int*)d_in[0];
    const int*   member_ids  = (const int*)d_in[1];
    const void*  member_mask = d_in[2];
    const float* user_table  = (const float*)d_in[3];
    const float* item_table  = (const float*)d_in[4];
    const float* W_bil       = (const float*)d_in[5];
    const float* b_bil       = (const float*)d_in[6];
    const float* W1          = (const float*)d_in[7];
    const float* b1          = (const float*)d_in[8];
    const float* W2          = (const float*)d_in[9];
    const float* b2          = (const float*)d_in[10];
    float* out = (float*)d_out;

    const int B  = in_sizes[0];
    int NI = in_sizes[4] / 32;
    if (NI > NI_CAP) NI = NI_CAP;

    int n_scan = in_sizes[2] / 4;      // ints readable under either mask layout
    if (n_scan > 1024) n_scan = 1024;

    precompute_kernel<<<(NI + 7) / 8, 256>>>(item_table, W_bil, W1,
                                             (const int*)member_mask, n_scan, NI);

    const int grid = (B + 31) / 32;    // 8 warps * 4 pairs per block
    bilinear_kernel<<<grid, 256>>>(item_inputs, member_ids, member_mask,
                                   user_table, item_table, b_bil,
                                   b1, W1, W2, b2, out, B);
}